// round 16
// baseline (speedup 1.0000x reference)
#include <cuda_runtime.h>
#include <cstdint>

// ---------------------------------------------------------------------------
// CTC loss (forward, sum over batch, zero_infinity) on GB300 — single fused
// kernel, SKEWED-WARP pipeline (no per-step CTA barrier).
//
// One CTA of 128 threads per batch element. Thread tid owns trellis columns
// 2*tid (blank: lse2, never skips) and 2*tid+1 (label: lse3). Log2-domain
// lse with exact median-of-3 (ex2 args <= 0: overflow/NaN free).
//
// Dependencies flow strictly left->right, so warp w runs one 8-step chunk
// BEHIND warp w-1. Cross-warp halo comes from a 32-entry per-warp history
// ring (lane 31 logs la1 each step; right warp's lane 0 reads it >=1 chunk
// later). Adjacent warps rendezvous once per chunk via named barriers
// (bar.sync id,64) -> pair lead <= 2 chunks (bounds all ring lifetimes and
// fences smem/cp.async visibility). NO __syncthreads in the hot loop.
//
// Emit gather fused: each thread cp.asyncs its own label value per row into
// a private ring slot (4-chunk x 8-row ring; 1 commit + 1 wait_group<2> per
// chunk). Blank values (shared) produced by warp 0 into a 128-row ring.
// ---------------------------------------------------------------------------

#define NEGF (-1.0e30f)
#define LOG2E 1.4426950408889634f
#define LN2   0.6931471805599453f
#define TPB   128

__device__ float g_loss[8192];
__device__ unsigned g_done;

__device__ __forceinline__ float ex2f(float x) {
    float r; asm("ex2.approx.f32 %0, %1;" : "=f"(r) : "f"(x)); return r;
}
__device__ __forceinline__ float lg2f(float x) {
    float r; asm("lg2.approx.f32 %0, %1;" : "=f"(r) : "f"(x)); return r;
}
__device__ __forceinline__ void cp4(uint32_t dst, const float* src) {
    asm volatile("cp.async.ca.shared.global [%0], [%1], 4;"
                 :: "r"(dst), "l"(src) : "memory");
}
__device__ __forceinline__ void cp_commit() {
    asm volatile("cp.async.commit_group;" ::: "memory");
}
template <int N>
__device__ __forceinline__ void cp_wait() {
    asm volatile("cp.async.wait_group %0;" :: "n"(N) : "memory");
}
__device__ __forceinline__ void barn(int id) {      // named rendezvous, 2 warps
    asm volatile("bar.sync %0, 64;" :: "r"(id) : "memory");
}

// log2-domain lse3, exact median-of-3 (both ex2 args <= 0).
__device__ __forceinline__ float lse3_2(float a0, float a1, float a2) {
    const float mx01 = fmaxf(a0, a1);
    const float mn01 = fminf(a0, a1);
    const float mx   = fmaxf(mx01, a2);
    const float md   = fmaxf(mn01, fminf(mx01, a2));
    const float mn   = fminf(mn01, a2);
    return mx + lg2f(1.0f + ex2f(md - mx) + ex2f(mn - mx));
}
// log2-domain lse2.
__device__ __forceinline__ float lse2_2(float a0, float a1) {
    const float mx = fmaxf(a0, a1);
    const float mn = fminf(a0, a1);
    return mx + lg2f(1.0f + ex2f(mn - mx));
}

__global__ void __launch_bounds__(TPB, 1)
ctc_fused_kernel(const float* __restrict__ logp,
                 const int*   __restrict__ targets,
                 const int*   __restrict__ input_lens,
                 const int*   __restrict__ target_lens,
                 float* __restrict__ out,
                 int B, int C, int S)
{
    __shared__ __align__(16) float ring_l[32][TPB];  // label logp ring, 16 KB
    __shared__ __align__(16) float ring_b[128];      // blank logp ring (warp0-fed)
    __shared__ float hist[4][32];                    // per-warp la1(lane31) history
    __shared__ float fin[2];
    __shared__ int   s_last;

    const int b    = blockIdx.x;
    const int tid  = threadIdx.x;
    const int lane = tid & 31;
    const int w    = tid >> 5;
    const unsigned FULL = 0xffffffffu;

    const int tl = target_lens[b];
    const int il = input_lens[b];
    const int Lb = 2 * tl + 1;
    const int NC = (il - 1 + 7) / 8;       // chunks of 8 steps

    const size_t strideT = (size_t)B * C;
    const float* rowbase = logp + (size_t)b * C;

    // Label + skip flag for odd column l1 = 2*tid+1 (even col never skips).
    int  e1  = 0;
    bool sk1 = false;
    if (tid < S) {
        e1 = targets[b * S + tid];
        const int l1 = 2 * tid + 1;
        if (l1 >= 3 && l1 < Lb) sk1 = (e1 != targets[b * S + tid - 1]);
    }
    const float* pl = rowbase + e1;

    const uint32_t rl0 = (uint32_t)__cvta_generic_to_shared(&ring_l[0][0]);
    const uint32_t rb0 = (uint32_t)__cvta_generic_to_shared(&ring_b[0]);

    // t = 0 init: columns 0,1 (thread 0); all else -1e30.
    float la0 = NEGF, la1 = NEGF;
    if (tid == 0) {
        la0 = rowbase[0] * LOG2E;
        la1 = pl[0] * LOG2E;
    }
    if (lane == 31) hist[w][0] = la1;      // post-"step 0" value, read at t=1
    if (tid == 0) { fin[1] = NEGF; s_last = 0; }

    // ---- Prologue: prefetch chunks 0..3 (rows 1..32), 1 commit group each ---
#pragma unroll
    for (int c = 0; c < 4; ++c) {
#pragma unroll
        for (int j = 0; j < 8; ++j) {
            const int row = min(8 * c + 1 + j, il - 1);
            cp4(rl0 + (uint32_t)((row - 1) & 31) * (TPB * 4u) + (uint32_t)tid * 4u,
                pl + (size_t)row * strideT);
            if (w == 0 && lane == j)
                cp4(rb0 + (uint32_t)((row - 1) & 127) * 4u,
                    rowbase + (size_t)row * strideT);
        }
        cp_commit();
    }
    __syncthreads();                       // init values (hist/fin/s_last) visible

    float erl = 0.0f, erb = 0.0f;

    // ---- Skewed chunk loop: no CTA barriers -----------------------------------
    for (int k = 0; k < NC; ++k) {
        if (w > 0) barn(w);                // gate: left warp finished chunk k
        cp_wait<2>();                      // own groups: chunks <= k+1 resident
        if (k == 0) {                      // stage row 1 (post gate: ring_b valid)
            erl = ring_l[0][tid];
            erb = ring_b[0];
        }
        const int pos = (8 * k) & 31;

#pragma unroll
        for (int j = 0; j < 8; ++j) {
            const int t = 8 * k + 1 + j;
            if (t < il) {                  // uniform across warp; no break
                // Halo: old la1 of column 2*tid-1.
                float P1 = __shfl_up_sync(FULL, la1, 1);
                if (lane == 0) P1 = (w > 0) ? hist[w - 1][(t - 1) & 31] : NEGF;

                const float t1 = lse3_2(la1, la0, sk1 ? P1 : NEGF);
                const float t0 = lse2_2(la0, P1);
                la1 = fmaf(erl, LOG2E, t1);
                la0 = fmaf(erb, LOG2E, t0);

                if (lane == 31) hist[w][t & 31] = la1;   // log for right warp

                // Stage row t+1.
                erl = ring_l[(pos + 1 + j) & 31][tid];
                erb = ring_b[t & 127];
            }
        }

        // Prefetch chunk k+4 (rows 8k+33..8k+40, clamped; idempotent at end).
#pragma unroll
        for (int j = 0; j < 8; ++j) {
            const int row = min(8 * k + 33 + j, il - 1);
            cp4(rl0 + (uint32_t)((row - 1) & 31) * (TPB * 4u) + (uint32_t)tid * 4u,
                pl + (size_t)row * strideT);
            if (w == 0 && lane == j)
                cp4(rb0 + (uint32_t)((row - 1) & 127) * 4u,
                    rowbase + (size_t)row * strideT);
        }
        cp_commit();

        if (w < 3) barn(w + 1);            // signal: my chunk k done
    }
    cp_wait<0>();                          // drain own groups

    // ---- Final cells: col 2*tl (thread tl, la0), col 2*tl-1 (thread tl-1, la1)
    if (tid == tl) fin[0] = la0;
    if (tl >= 1 && tid == tl - 1) fin[1] = la1;
    __syncthreads();

    if (tid == 0) {
        const float x1 = fin[0];
        const float x2 = fin[1];
        const float m  = fmaxf(x1, x2);
        float loss = -LN2 * (m + lg2f(ex2f(x1 - m) + ex2f(x2 - m)));
        if (!(loss < 5.0e29f)) loss = 0.0f;        // zero_infinity
        g_loss[b] = loss;
        __threadfence();
        const unsigned n = atomicAdd(&g_done, 1u);
        if (n == (unsigned)(gridDim.x - 1)) s_last = 1;
    }
    __syncthreads();

    // Last-arriving CTA: warp 0 reduces g_loss -> out[0].
    if (s_last && w == 0) {
        float s = 0.0f;
        for (int i = lane; i < B; i += 32) s += g_loss[i];
#pragma unroll
        for (int o = 16; o; o >>= 1) s += __shfl_xor_sync(FULL, s, o);
        if (lane == 0) {
            out[0] = s;
            g_done = 0u;
        }
    }
}

extern "C" void kernel_launch(void* const* d_in, const int* in_sizes, int n_in,
                              void* d_out, int out_size)
{
    const float* logp        = (const float*)d_in[0];
    const int*   targets     = (const int*)  d_in[1];
    const int*   input_lens  = (const int*)  d_in[2];
    const int*   target_lens = (const int*)  d_in[3];

    const int B = in_sizes[2];
    const int S = in_sizes[1] / B;
    const int C = 1000;                   // class count (dataset constant)

    ctc_fused_kernel<<<B, TPB>>>(logp, targets, input_lens, target_lens,
                                 (float*)d_out, B, C, S);
}